// round 9
// baseline (speedup 1.0000x reference)
#include <cuda_runtime.h>
#include <cuda_bf16.h>
#include <cstdint>

// ---------------------------------------------------------------------------
#define NB   32
#define C    1024
#define S    1024
#define BM   128
#define BN   128
#define BKB  128                      // K-chunk in BYTES (=128 int8 elems)
#define NCHUNK (S / BKB)              // 8
#define TILES_PER_BATCH 36
#define NBLK2 (NB * TILES_PER_BATCH)  // 1152
#define NSM   148
#define GRID  (2 * NSM)               // 296 — ALL resident (2/SM), required
#define TPB   320                     // 8 gram warps + 2 producer warps
#define GTPB  256                     // gram threads
#define NPRODW (2 * GRID)             // 592 producer warps
#define STAGES 3
#define TILE_BYTES (BM * BKB)         // 16384
#define STAGE_BYTES (2 * TILE_BYTES)
#define DSMEM_BYTES (STAGES * STAGE_BYTES)   // 98304

// Scratch
__device__ int8_t g_xq[(size_t)NB * C * S];
__device__ float  g_scale[NB * C];
__device__ float  g_partials[NBLK2];
__device__ int    g_done[NB];

// ---------------------------------------------------------------------------
__device__ __forceinline__ void cp_async16(uint32_t smem_addr, const void* gptr) {
    asm volatile("cp.async.cg.shared.global [%0], [%1], 16;" :: "r"(smem_addr), "l"(gptr));
}
#define CP_COMMIT() asm volatile("cp.async.commit_group;" ::: "memory")
#define CP_WAIT(n)  asm volatile("cp.async.wait_group %0;" :: "n"(n) : "memory")
#define BARG()      asm volatile("bar.sync 1, 256;" ::: "memory")   // gram-warp barrier

__device__ __forceinline__ void ldm_x4(uint32_t& r0, uint32_t& r1, uint32_t& r2, uint32_t& r3,
                                       uint32_t addr) {
    asm volatile("ldmatrix.sync.aligned.m8n8.x4.shared.b16 {%0,%1,%2,%3}, [%4];\n"
                 : "=r"(r0), "=r"(r1), "=r"(r2), "=r"(r3) : "r"(addr));
}

__device__ __forceinline__ void mma16832_s8(int* d, const uint32_t* a, const uint32_t* b) {
    asm volatile("mma.sync.aligned.m16n8k32.row.col.s32.s8.s8.s32 "
                 "{%0,%1,%2,%3}, {%4,%5,%6,%7}, {%8,%9}, {%0,%1,%2,%3};\n"
                 : "+r"(d[0]), "+r"(d[1]), "+r"(d[2]), "+r"(d[3])
                 : "r"(a[0]), "r"(a[1]), "r"(a[2]), "r"(a[3]), "r"(b[0]), "r"(b[1]));
}

__device__ __forceinline__ uint32_t swzB(int row, int byteoff) {
    uint32_t chunk = (uint32_t)(byteoff >> 4);
    return (uint32_t)(row * 128) + ((chunk ^ ((uint32_t)row & 7u)) << 4);
}

// ---------------------------------------------------------------------------
// zero the per-batch readiness counters (replay-safe)
// ---------------------------------------------------------------------------
__global__ void zero_kernel() {
    if (threadIdx.x < NB) g_done[threadIdx.x] = 0;
}

// ---------------------------------------------------------------------------
// Fused persistent kernel.
//  warps 0-7  : gram consumers (int8 mma pipeline, named barrier 1)
//  warps 8-9  : normalize producers (2 rows in flight, per-batch counters)
// ---------------------------------------------------------------------------
__global__ __launch_bounds__(TPB, 2) void fused_kernel(const float* __restrict__ x) {
    extern __shared__ __align__(128) char dsmem[];
    __shared__ float sScA[BM];
    __shared__ float sScB[BN];
    __shared__ float s_red[8];

    const int tid  = threadIdx.x;
    const int wid  = tid >> 5;
    const int lane = tid & 31;

    // ======================= PRODUCER WARPS =======================
    if (wid >= 8) {
        const int gw = blockIdx.x * 2 + (wid - 8);        // 0..591
        for (int p = gw; 2 * p < NB * C; p += NPRODW) {
            const int r0 = 2 * p;
            const int batch = r0 >> 10;                   // row / C
            const float4* in0 = reinterpret_cast<const float4*>(x + (size_t)r0 * S);
            const float4* in1 = reinterpret_cast<const float4*>(x + (size_t)(r0 + 1) * S);

            float4 v0[8], v1[8];
            #pragma unroll
            for (int i = 0; i < 8; i++) { v0[i] = in0[lane + 32 * i]; v1[i] = in1[lane + 32 * i]; }

            float s0 = 0.f, ss0 = 0.f, s1 = 0.f, ss1 = 0.f;
            #pragma unroll
            for (int i = 0; i < 8; i++) {
                s0  += v0[i].x + v0[i].y + v0[i].z + v0[i].w;
                ss0 += v0[i].x*v0[i].x + v0[i].y*v0[i].y + v0[i].z*v0[i].z + v0[i].w*v0[i].w;
                s1  += v1[i].x + v1[i].y + v1[i].z + v1[i].w;
                ss1 += v1[i].x*v1[i].x + v1[i].y*v1[i].y + v1[i].z*v1[i].z + v1[i].w*v1[i].w;
            }
            #pragma unroll
            for (int o = 16; o; o >>= 1) {
                s0  += __shfl_xor_sync(0xFFFFFFFFu, s0,  o);
                ss0 += __shfl_xor_sync(0xFFFFFFFFu, ss0, o);
                s1  += __shfl_xor_sync(0xFFFFFFFFu, s1,  o);
                ss1 += __shfl_xor_sync(0xFFFFFFFFu, ss1, o);
            }
            const float mean0 = s0 * (1.0f / S);
            const float mean1 = s1 * (1.0f / S);

            float mx0 = 0.f, mx1 = 0.f;
            #pragma unroll
            for (int i = 0; i < 8; i++) {
                mx0 = fmaxf(mx0, fmaxf(fmaxf(fabsf(v0[i].x - mean0), fabsf(v0[i].y - mean0)),
                                       fmaxf(fabsf(v0[i].z - mean0), fabsf(v0[i].w - mean0))));
                mx1 = fmaxf(mx1, fmaxf(fmaxf(fabsf(v1[i].x - mean1), fabsf(v1[i].y - mean1)),
                                       fmaxf(fabsf(v1[i].z - mean1), fabsf(v1[i].w - mean1))));
            }
            #pragma unroll
            for (int o = 16; o; o >>= 1) {
                mx0 = fmaxf(mx0, __shfl_xor_sync(0xFFFFFFFFu, mx0, o));
                mx1 = fmaxf(mx1, __shfl_xor_sync(0xFFFFFFFFu, mx1, o));
            }
            mx0 = fmaxf(mx0, 1e-20f);
            mx1 = fmaxf(mx1, 1e-20f);

            const float inv_nrm0 = 1.0f / (sqrtf(fmaxf(ss0 - s0 * mean0, 0.0f)) + 1e-8f);
            const float inv_nrm1 = 1.0f / (sqrtf(fmaxf(ss1 - s1 * mean1, 0.0f)) + 1e-8f);
            const float q0 = 127.0f / mx0;
            const float q1 = 127.0f / mx1;

            if (lane == 0) {
                g_scale[r0]     = mx0 * inv_nrm0 * (1.0f / 127.0f);
                g_scale[r0 + 1] = mx1 * inv_nrm1 * (1.0f / 127.0f);
            }

            uint32_t* o0 = reinterpret_cast<uint32_t*>(g_xq + (size_t)r0 * S);
            uint32_t* o1 = reinterpret_cast<uint32_t*>(g_xq + (size_t)(r0 + 1) * S);
            #pragma unroll
            for (int i = 0; i < 8; i++) {
                int a0 = __float2int_rn((v0[i].x - mean0) * q0);
                int a1 = __float2int_rn((v0[i].y - mean0) * q0);
                int a2 = __float2int_rn((v0[i].z - mean0) * q0);
                int a3 = __float2int_rn((v0[i].w - mean0) * q0);
                o0[lane + 32 * i] = (a0 & 0xFF) | ((a1 & 0xFF) << 8) | ((a2 & 0xFF) << 16)
                                  | (((uint32_t)a3 & 0xFF) << 24);
                int b0 = __float2int_rn((v1[i].x - mean1) * q1);
                int b1 = __float2int_rn((v1[i].y - mean1) * q1);
                int b2 = __float2int_rn((v1[i].z - mean1) * q1);
                int b3 = __float2int_rn((v1[i].w - mean1) * q1);
                o1[lane + 32 * i] = (b0 & 0xFF) | ((b1 & 0xFF) << 8) | ((b2 & 0xFF) << 16)
                                  | (((uint32_t)b3 & 0xFF) << 24);
            }
            __threadfence();                      // release rows to L2
            if (lane == 0) atomicAdd(&g_done[batch], 2);
        }
        return;
    }

    // ======================= GRAM CONSUMER WARPS (tid < 256) =======================
    const int warp_m = wid & 1;
    const int warp_n = wid >> 1;
    const uint32_t smem_base = (uint32_t)__cvta_generic_to_shared(dsmem);

    const int a_row  = warp_m * 64 + (lane & 15);
    const int a_colB = (lane >> 4) * 16;
    const int b_row  = warp_n * 32 + (lane & 7) + ((lane >> 4) << 3);
    const int b_colB = ((lane >> 3) & 1) * 16;

    for (int k = 0;; k++) {
        const int idx = blockIdx.x + GRID * k;
        if (idx >= NBLK2) break;

        const int batch = idx / TILES_PER_BATCH;
        int t = idx % TILES_PER_BATCH;
        int ti = 0;
        while (t >= 8 - ti) { t -= 8 - ti; ti++; }
        const int tj = ti + t;
        const bool diag = (ti == tj);

        // wait until this batch's rows are quantized (acquire via atomic)
        if (tid == 0) {
            while (atomicAdd(&g_done[batch], 0) < C) __nanosleep(256);
        }
        BARG();   // all gram threads ordered after readiness; also protects stage reuse

        const int8_t* gA = g_xq + ((size_t)batch * C + ti * BM) * S;
        const int8_t* gB = g_xq + ((size_t)batch * C + tj * BN) * S;

        if (tid < BM) sScA[tid] = g_scale[batch * C + ti * BM + tid];
        else          sScB[tid - BM] = g_scale[batch * C + tj * BN + (tid - BM)];

        auto load_chunk = [&](int cch, int stage) {
            const int k0 = cch * BKB;
            const uint32_t sA = smem_base + stage * STAGE_BYTES;
            const uint32_t sB = sA + TILE_BYTES;
            #pragma unroll
            for (int it = 0; it < 4; it++) {
                int i2  = it * GTPB + tid;
                int r   = i2 >> 3;
                int c16 = i2 & 7;
                uint32_t dst = swzB(r, c16 * 16);
                const size_t goff = (size_t)r * S + k0 + c16 * 16;
                cp_async16(sA + dst, gA + goff);
                if (!diag) cp_async16(sB + dst, gB + goff);
            }
        };

        int acc[4][4][4];
        #pragma unroll
        for (int i = 0; i < 4; i++)
            #pragma unroll
            for (int j = 0; j < 4; j++)
                #pragma unroll
                for (int r = 0; r < 4; r++) acc[i][j][r] = 0;

        load_chunk(0, 0); CP_COMMIT();
        load_chunk(1, 1); CP_COMMIT();

        for (int cch = 0; cch < NCHUNK; cch++) {
            const int stage = cch % STAGES;
            CP_WAIT(1);
            BARG();   // chunk cch resident; compute(cch-1) done by all gram warps

            if (cch + 2 < NCHUNK) {
                load_chunk(cch + 2, (cch + 2) % STAGES);
                CP_COMMIT();
            }

            const uint32_t sA = smem_base + stage * STAGE_BYTES;
            const uint32_t sB = diag ? sA : (sA + TILE_BYTES);

            #pragma unroll
            for (int kk = 0; kk < 4; kk++) {
                const int kb = kk * 32;
                uint32_t a[4][4];
                #pragma unroll
                for (int mf = 0; mf < 4; mf++) {
                    uint32_t addr = sA + swzB(a_row + mf * 16, kb + a_colB);
                    ldm_x4(a[mf][0], a[mf][1], a[mf][2], a[mf][3], addr);
                }
                uint32_t b[4][2];
                {
                    uint32_t addr0 = sB + swzB(b_row, kb + b_colB);
                    ldm_x4(b[0][0], b[0][1], b[1][0], b[1][1], addr0);
                    uint32_t addr1 = sB + swzB(b_row + 16, kb + b_colB);
                    ldm_x4(b[2][0], b[2][1], b[3][0], b[3][1], addr1);
                }
                #pragma unroll
                for (int mf = 0; mf < 4; mf++)
                    #pragma unroll
                    for (int nf = 0; nf < 4; nf++)
                        mma16832_s8(acc[mf][nf], a[mf], b[nf]);
            }
        }

        // Epilogue: rescale, mask strictly-upper, abs-sum
        const int groupID = lane >> 2;
        const int tid4    = lane & 3;
        float lsum = 0.0f;
        #pragma unroll
        for (int mf = 0; mf < 4; mf++) {
            const int li0 = warp_m * 64 + mf * 16 + groupID;
            const int li1 = li0 + 8;
            const float sa0 = sScA[li0];
            const float sa1 = sScA[li1];
            const int gi0 = ti * BM + li0;
            const int gi1 = ti * BM + li1;
            #pragma unroll
            for (int nf = 0; nf < 4; nf++) {
                const int lj = warp_n * 32 + nf * 8 + tid4 * 2;
                const int gj = tj * BN + lj;
                const float sb0 = sScB[lj];
                const float sb1 = sScB[lj + 1];
                if (gj     > gi0) lsum += fabsf((float)acc[mf][nf][0] * sa0 * sb0);
                if (gj + 1 > gi0) lsum += fabsf((float)acc[mf][nf][1] * sa0 * sb1);
                if (gj     > gi1) lsum += fabsf((float)acc[mf][nf][2] * sa1 * sb0);
                if (gj + 1 > gi1) lsum += fabsf((float)acc[mf][nf][3] * sa1 * sb1);
            }
        }
        #pragma unroll
        for (int o = 16; o; o >>= 1) lsum += __shfl_xor_sync(0xFFFFFFFFu, lsum, o);

        if (lane == 0) s_red[wid] = lsum;
        BARG();
        if (tid == 0) {
            float bsum = 0.f;
            #pragma unroll
            for (int w = 0; w < 8; w++) bsum += s_red[w];
            g_partials[idx] = bsum;
        }
        // next iteration's post-spin BARG orders epilogue before stage/s_red reuse
    }
}

// ---------------------------------------------------------------------------
__global__ __launch_bounds__(256) void finalize_kernel(float* __restrict__ out) {
    float s = 0.0f;
    for (int i = threadIdx.x; i < NBLK2; i += 256) s += g_partials[i];
    #pragma unroll
    for (int o = 16; o; o >>= 1) s += __shfl_xor_sync(0xFFFFFFFFu, s, o);

    __shared__ float red[8];
    const int wid = threadIdx.x >> 5;
    if ((threadIdx.x & 31) == 0) red[wid] = s;
    __syncthreads();
    if (threadIdx.x == 0) {
        float tot = 0.f;
        #pragma unroll
        for (int w = 0; w < 8; w++) tot += red[w];
        const float comb = (float)C * (C - 1) * 0.5f;
        out[0] = tot / (comb * (float)NB);
    }
}

// ---------------------------------------------------------------------------
extern "C" void kernel_launch(void* const* d_in, const int* in_sizes, int n_in,
                              void* d_out, int out_size) {
    const float* x = (const float*)d_in[0];
    float* out = (float*)d_out;

    cudaFuncSetAttribute(fused_kernel,
                         cudaFuncAttributeMaxDynamicSharedMemorySize, DSMEM_BYTES);

    zero_kernel<<<1, 32>>>();
    fused_kernel<<<GRID, TPB, DSMEM_BYTES>>>(x);
    finalize_kernel<<<1, 256>>>(out);
}

// round 10
// speedup vs baseline: 1.0018x; 1.0018x over previous
#include <cuda_runtime.h>
#include <cuda_bf16.h>
#include <cstdint>

// ---------------------------------------------------------------------------
#define NB   32
#define C    1024
#define S    1024
#define BM   128
#define BN   128
#define BKB  128                      // K-chunk in BYTES (=128 int8 elems)
#define NCHUNK (S / BKB)              // 8
#define TILES_PER_BATCH 36
#define NBLK2 (NB * TILES_PER_BATCH)  // 1152
#define GRID  148                     // 1 block/SM, ALL resident (deadlock-free)
#define TPB   384                     // 8 gram warps + 4 producer warps
#define GTPB  256                     // gram threads
#define NPRODW (4 * GRID)             // 592 producer warps
#define STAGES 3
#define TILE_BYTES (BM * BKB)         // 16384
#define STAGE_BYTES (2 * TILE_BYTES)
#define DSMEM_BYTES (STAGES * STAGE_BYTES)   // 98304

// Scratch
__device__ int8_t g_xq[(size_t)NB * C * S];
__device__ float  g_scale[NB * C];
__device__ float  g_partials[NBLK2];
__device__ int    g_done[NB];
__device__ int    g_tile;

// ---------------------------------------------------------------------------
__device__ __forceinline__ void cp_async16(uint32_t smem_addr, const void* gptr) {
    asm volatile("cp.async.cg.shared.global [%0], [%1], 16;" :: "r"(smem_addr), "l"(gptr));
}
#define CP_COMMIT() asm volatile("cp.async.commit_group;" ::: "memory")
#define CP_WAIT(n)  asm volatile("cp.async.wait_group %0;" :: "n"(n) : "memory")
#define BARG()      asm volatile("bar.sync 1, 256;" ::: "memory")   // gram-warp barrier

__device__ __forceinline__ void ldm_x4(uint32_t& r0, uint32_t& r1, uint32_t& r2, uint32_t& r3,
                                       uint32_t addr) {
    asm volatile("ldmatrix.sync.aligned.m8n8.x4.shared.b16 {%0,%1,%2,%3}, [%4];\n"
                 : "=r"(r0), "=r"(r1), "=r"(r2), "=r"(r3) : "r"(addr));
}

__device__ __forceinline__ void mma16832_s8(int* d, const uint32_t* a, const uint32_t* b) {
    asm volatile("mma.sync.aligned.m16n8k32.row.col.s32.s8.s8.s32 "
                 "{%0,%1,%2,%3}, {%4,%5,%6,%7}, {%8,%9}, {%0,%1,%2,%3};\n"
                 : "+r"(d[0]), "+r"(d[1]), "+r"(d[2]), "+r"(d[3])
                 : "r"(a[0]), "r"(a[1]), "r"(a[2]), "r"(a[3]), "r"(b[0]), "r"(b[1]));
}

__device__ __forceinline__ uint32_t swzB(int row, int byteoff) {
    uint32_t chunk = (uint32_t)(byteoff >> 4);
    return (uint32_t)(row * 128) + ((chunk ^ ((uint32_t)row & 7u)) << 4);
}

// ---------------------------------------------------------------------------
// reset readiness counters + tile counter (replay-safe)
// ---------------------------------------------------------------------------
__global__ void zero_kernel() {
    if (threadIdx.x < NB) g_done[threadIdx.x] = 0;
    if (threadIdx.x == NB) g_tile = 0;
}

// ---------------------------------------------------------------------------
// Fused persistent kernel, 1 block/SM.
//  warps 0-7  : gram consumers (dynamic tile queue, named barrier 1)
//  warps 8-11 : normalize producers (2 rows in flight each)
// ---------------------------------------------------------------------------
__global__ __launch_bounds__(TPB, 1) void fused_kernel(const float* __restrict__ x) {
    extern __shared__ __align__(128) char dsmem[];
    __shared__ float sScA[BM];
    __shared__ float sScB[BN];
    __shared__ float s_red[8];
    __shared__ int   s_idx;

    const int tid  = threadIdx.x;
    const int wid  = tid >> 5;
    const int lane = tid & 31;

    // ======================= PRODUCER WARPS =======================
    if (wid >= 8) {
        const int gw = blockIdx.x * 4 + (wid - 8);        // 0..591
        for (int p = gw; 2 * p < NB * C; p += NPRODW) {
            const int r0 = 2 * p;
            const int batch = r0 >> 10;
            const float4* in0 = reinterpret_cast<const float4*>(x + (size_t)r0 * S);
            const float4* in1 = reinterpret_cast<const float4*>(x + (size_t)(r0 + 1) * S);

            float4 v0[8], v1[8];
            #pragma unroll
            for (int i = 0; i < 8; i++) { v0[i] = in0[lane + 32 * i]; v1[i] = in1[lane + 32 * i]; }

            float s0 = 0.f, ss0 = 0.f, s1 = 0.f, ss1 = 0.f;
            #pragma unroll
            for (int i = 0; i < 8; i++) {
                s0  += v0[i].x + v0[i].y + v0[i].z + v0[i].w;
                ss0 += v0[i].x*v0[i].x + v0[i].y*v0[i].y + v0[i].z*v0[i].z + v0[i].w*v0[i].w;
                s1  += v1[i].x + v1[i].y + v1[i].z + v1[i].w;
                ss1 += v1[i].x*v1[i].x + v1[i].y*v1[i].y + v1[i].z*v1[i].z + v1[i].w*v1[i].w;
            }
            #pragma unroll
            for (int o = 16; o; o >>= 1) {
                s0  += __shfl_xor_sync(0xFFFFFFFFu, s0,  o);
                ss0 += __shfl_xor_sync(0xFFFFFFFFu, ss0, o);
                s1  += __shfl_xor_sync(0xFFFFFFFFu, s1,  o);
                ss1 += __shfl_xor_sync(0xFFFFFFFFu, ss1, o);
            }
            const float mean0 = s0 * (1.0f / S);
            const float mean1 = s1 * (1.0f / S);

            float mx0 = 0.f, mx1 = 0.f;
            #pragma unroll
            for (int i = 0; i < 8; i++) {
                mx0 = fmaxf(mx0, fmaxf(fmaxf(fabsf(v0[i].x - mean0), fabsf(v0[i].y - mean0)),
                                       fmaxf(fabsf(v0[i].z - mean0), fabsf(v0[i].w - mean0))));
                mx1 = fmaxf(mx1, fmaxf(fmaxf(fabsf(v1[i].x - mean1), fabsf(v1[i].y - mean1)),
                                       fmaxf(fabsf(v1[i].z - mean1), fabsf(v1[i].w - mean1))));
            }
            #pragma unroll
            for (int o = 16; o; o >>= 1) {
                mx0 = fmaxf(mx0, __shfl_xor_sync(0xFFFFFFFFu, mx0, o));
                mx1 = fmaxf(mx1, __shfl_xor_sync(0xFFFFFFFFu, mx1, o));
            }
            mx0 = fmaxf(mx0, 1e-20f);
            mx1 = fmaxf(mx1, 1e-20f);

            const float inv_nrm0 = 1.0f / (sqrtf(fmaxf(ss0 - s0 * mean0, 0.0f)) + 1e-8f);
            const float inv_nrm1 = 1.0f / (sqrtf(fmaxf(ss1 - s1 * mean1, 0.0f)) + 1e-8f);
            const float q0 = 127.0f / mx0;
            const float q1 = 127.0f / mx1;

            if (lane == 0) {
                g_scale[r0]     = mx0 * inv_nrm0 * (1.0f / 127.0f);
                g_scale[r0 + 1] = mx1 * inv_nrm1 * (1.0f / 127.0f);
            }

            uint32_t* o0 = reinterpret_cast<uint32_t*>(g_xq + (size_t)r0 * S);
            uint32_t* o1 = reinterpret_cast<uint32_t*>(g_xq + (size_t)(r0 + 1) * S);
            #pragma unroll
            for (int i = 0; i < 8; i++) {
                int a0 = __float2int_rn((v0[i].x - mean0) * q0);
                int a1 = __float2int_rn((v0[i].y - mean0) * q0);
                int a2 = __float2int_rn((v0[i].z - mean0) * q0);
                int a3 = __float2int_rn((v0[i].w - mean0) * q0);
                o0[lane + 32 * i] = (a0 & 0xFF) | ((a1 & 0xFF) << 8) | ((a2 & 0xFF) << 16)
                                  | (((uint32_t)a3 & 0xFF) << 24);
                int b0 = __float2int_rn((v1[i].x - mean1) * q1);
                int b1 = __float2int_rn((v1[i].y - mean1) * q1);
                int b2 = __float2int_rn((v1[i].z - mean1) * q1);
                int b3 = __float2int_rn((v1[i].w - mean1) * q1);
                o1[lane + 32 * i] = (b0 & 0xFF) | ((b1 & 0xFF) << 8) | ((b2 & 0xFF) << 16)
                                  | (((uint32_t)b3 & 0xFF) << 24);
            }
            __threadfence();                      // release rows before counter bump
            if (lane == 0) atomicAdd(&g_done[batch], 2);
        }
        return;
    }

    // ======================= GRAM CONSUMER WARPS (tid < 256) =======================
    const int warp_m = wid & 1;
    const int warp_n = wid >> 1;
    const uint32_t smem_base = (uint32_t)__cvta_generic_to_shared(dsmem);

    const int a_row  = warp_m * 64 + (lane & 15);
    const int a_colB = (lane >> 4) * 16;
    const int b_row  = warp_n * 32 + (lane & 7) + ((lane >> 4) << 3);
    const int b_colB = ((lane >> 3) & 1) * 16;

    for (;;) {
        // dynamic tile fetch + readiness spin (tid 0), broadcast via smem
        if (tid == 0) {
            int idx = atomicAdd(&g_tile, 1);
            if (idx < NBLK2) {
                const int batch = idx / TILES_PER_BATCH;
                while (atomicAdd(&g_done[batch], 0) < C) __nanosleep(128);
                __threadfence();   // acquire: order tile loads after readiness
            }
            s_idx = idx;
        }
        BARG();                     // broadcast idx; also protects stage/s_red reuse
        const int idx = s_idx;
        if (idx >= NBLK2) break;

        const int batch = idx / TILES_PER_BATCH;
        int t = idx % TILES_PER_BATCH;
        int ti = 0;
        while (t >= 8 - ti) { t -= 8 - ti; ti++; }
        const int tj = ti + t;
        const bool diag = (ti == tj);

        const int8_t* gA = g_xq + ((size_t)batch * C + ti * BM) * S;
        const int8_t* gB = g_xq + ((size_t)batch * C + tj * BN) * S;

        if (tid < BM) sScA[tid] = g_scale[batch * C + ti * BM + tid];
        else          sScB[tid - BM] = g_scale[batch * C + tj * BN + (tid - BM)];

        auto load_chunk = [&](int cch, int stage) {
            const int k0 = cch * BKB;
            const uint32_t sA = smem_base + stage * STAGE_BYTES;
            const uint32_t sB = sA + TILE_BYTES;
            #pragma unroll
            for (int it = 0; it < 4; it++) {
                int i2  = it * GTPB + tid;
                int r   = i2 >> 3;
                int c16 = i2 & 7;
                uint32_t dst = swzB(r, c16 * 16);
                const size_t goff = (size_t)r * S + k0 + c16 * 16;
                cp_async16(sA + dst, gA + goff);
                if (!diag) cp_async16(sB + dst, gB + goff);
            }
        };

        int acc[4][4][4];
        #pragma unroll
        for (int i = 0; i < 4; i++)
            #pragma unroll
            for (int j = 0; j < 4; j++)
                #pragma unroll
                for (int r = 0; r < 4; r++) acc[i][j][r] = 0;

        load_chunk(0, 0); CP_COMMIT();
        load_chunk(1, 1); CP_COMMIT();

        for (int cch = 0; cch < NCHUNK; cch++) {
            const int stage = cch % STAGES;
            CP_WAIT(1);
            BARG();   // chunk cch resident; compute(cch-1) done by all gram warps

            if (cch + 2 < NCHUNK) {
                load_chunk(cch + 2, (cch + 2) % STAGES);
                CP_COMMIT();
            }

            const uint32_t sA = smem_base + stage * STAGE_BYTES;
            const uint32_t sB = diag ? sA : (sA + TILE_BYTES);

            #pragma unroll
            for (int kk = 0; kk < 4; kk++) {
                const int kb = kk * 32;
                uint32_t a[4][4];
                #pragma unroll
                for (int mf = 0; mf < 4; mf++) {
                    uint32_t addr = sA + swzB(a_row + mf * 16, kb + a_colB);
                    ldm_x4(a[mf][0], a[mf][1], a[mf][2], a[mf][3], addr);
                }
                uint32_t b[4][2];
                {
                    uint32_t addr0 = sB + swzB(b_row, kb + b_colB);
                    ldm_x4(b[0][0], b[0][1], b[1][0], b[1][1], addr0);
                    uint32_t addr1 = sB + swzB(b_row + 16, kb + b_colB);
                    ldm_x4(b[2][0], b[2][1], b[3][0], b[3][1], addr1);
                }
                #pragma unroll
                for (int mf = 0; mf < 4; mf++)
                    #pragma unroll
                    for (int nf = 0; nf < 4; nf++)
                        mma16832_s8(acc[mf][nf], a[mf], b[nf]);
            }
        }

        // Epilogue: rescale, mask strictly-upper, abs-sum
        const int groupID = lane >> 2;
        const int tid4    = lane & 3;
        float lsum = 0.0f;
        #pragma unroll
        for (int mf = 0; mf < 4; mf++) {
            const int li0 = warp_m * 64 + mf * 16 + groupID;
            const int li1 = li0 + 8;
            const float sa0 = sScA[li0];
            const float sa1 = sScA[li1];
            const int gi0 = ti * BM + li0;
            const int gi1 = ti * BM + li1;
            #pragma unroll
            for (int nf = 0; nf < 4; nf++) {
                const int lj = warp_n * 32 + nf * 8 + tid4 * 2;
                const int gj = tj * BN + lj;
                const float sb0 = sScB[lj];
                const float sb1 = sScB[lj + 1];
                if (gj     > gi0) lsum += fabsf((float)acc[mf][nf][0] * sa0 * sb0);
                if (gj + 1 > gi0) lsum += fabsf((float)acc[mf][nf][1] * sa0 * sb1);
                if (gj     > gi1) lsum += fabsf((float)acc[mf][nf][2] * sa1 * sb0);
                if (gj + 1 > gi1) lsum += fabsf((float)acc[mf][nf][3] * sa1 * sb1);
            }
        }
        #pragma unroll
        for (int o = 16; o; o >>= 1) lsum += __shfl_xor_sync(0xFFFFFFFFu, lsum, o);

        if (lane == 0) s_red[wid] = lsum;
        BARG();
        if (tid == 0) {
            float bsum = 0.f;
            #pragma unroll
            for (int w = 0; w < 8; w++) bsum += s_red[w];
            g_partials[idx] = bsum;
        }
        // next iteration's top BARG orders epilogue before stage/s_red reuse
    }
}

// ---------------------------------------------------------------------------
__global__ __launch_bounds__(256) void finalize_kernel(float* __restrict__ out) {
    float s = 0.0f;
    for (int i = threadIdx.x; i < NBLK2; i += 256) s += g_partials[i];
    #pragma unroll
    for (int o = 16; o; o >>= 1) s += __shfl_xor_sync(0xFFFFFFFFu, s, o);

    __shared__ float red[8];
    const int wid = threadIdx.x >> 5;
    if ((threadIdx.x & 31) == 0) red[wid] = s;
    __syncthreads();
    if (threadIdx.x == 0) {
        float tot = 0.f;
        #pragma unroll
        for (int w = 0; w < 8; w++) tot += red[w];
        const float comb = (float)C * (C - 1) * 0.5f;
        out[0] = tot / (comb * (float)NB);
    }
}

// ---------------------------------------------------------------------------
extern "C" void kernel_launch(void* const* d_in, const int* in_sizes, int n_in,
                              void* d_out, int out_size) {
    const float* x = (const float*)d_in[0];
    float* out = (float*)d_out;

    cudaFuncSetAttribute(fused_kernel,
                         cudaFuncAttributeMaxDynamicSharedMemorySize, DSMEM_BYTES);

    zero_kernel<<<1, 64>>>();
    fused_kernel<<<GRID, TPB, DSMEM_BYTES>>>(x);
    finalize_kernel<<<1, 256>>>(out);
}

// round 12
// speedup vs baseline: 1.2439x; 1.2416x over previous
#include <cuda_runtime.h>
#include <cuda_bf16.h>
#include <cstdint>

// ---------------------------------------------------------------------------
#define NB   32
#define C    1024
#define S    1024
#define BM   128
#define BN   128
#define BKB  128                      // K-chunk in BYTES (=128 int8 elems)
#define NCHUNK (S / BKB)              // 8
#define TILES_PER_BATCH 36
#define NBLK2 (NB * TILES_PER_BATCH)  // 1152
#define TPB  256
#define STAGES 3
#define TILE_BYTES (BM * BKB)         // 16384
#define STAGE_BYTES (2 * TILE_BYTES)
#define DSMEM_BYTES (STAGES * STAGE_BYTES)   // 98304

// Scratch: int8 normalized rows (32 MB) + per-row scales + partials
__device__ int8_t g_xq[(size_t)NB * C * S];
__device__ float  g_scale[NB * C];
__device__ float  g_partials[NBLK2];

// ---------------------------------------------------------------------------
__device__ __forceinline__ void cp_async16(uint32_t smem_addr, const void* gptr) {
    asm volatile("cp.async.cg.shared.global [%0], [%1], 16;" :: "r"(smem_addr), "l"(gptr));
}
#define CP_COMMIT() asm volatile("cp.async.commit_group;" ::: "memory")
#define CP_WAIT(n)  asm volatile("cp.async.wait_group %0;" :: "n"(n) : "memory")

__device__ __forceinline__ void ldm_x4(uint32_t& r0, uint32_t& r1, uint32_t& r2, uint32_t& r3,
                                       uint32_t addr) {
    asm volatile("ldmatrix.sync.aligned.m8n8.x4.shared.b16 {%0,%1,%2,%3}, [%4];\n"
                 : "=r"(r0), "=r"(r1), "=r"(r2), "=r"(r3) : "r"(addr));
}

// int8 MMA: m16n8k32, s32 accumulate (exact)
__device__ __forceinline__ void mma16832_s8(int* d, const uint32_t* a, const uint32_t* b) {
    asm volatile("mma.sync.aligned.m16n8k32.row.col.s32.s8.s8.s32 "
                 "{%0,%1,%2,%3}, {%4,%5,%6,%7}, {%8,%9}, {%0,%1,%2,%3};\n"
                 : "+r"(d[0]), "+r"(d[1]), "+r"(d[2]), "+r"(d[3])
                 : "r"(a[0]), "r"(a[1]), "r"(a[2]), "r"(a[3]), "r"(b[0]), "r"(b[1]));
}

// XOR swizzle for 128B rows; byteoff must be a multiple of 16
__device__ __forceinline__ uint32_t swzB(int row, int byteoff) {
    uint32_t chunk = (uint32_t)(byteoff >> 4);
    return (uint32_t)(row * 128) + ((chunk ^ ((uint32_t)row & 7u)) << 4);
}

// ---------------------------------------------------------------------------
// Kernel 1: normalize + int8 quantize — one warp per row (at bandwidth ceiling)
// ---------------------------------------------------------------------------
__global__ __launch_bounds__(256) void normalize_kernel(const float* __restrict__ x) {
    const int wid  = threadIdx.x >> 5;
    const int lane = threadIdx.x & 31;
    const int row  = blockIdx.x * 8 + wid;
    const size_t base = (size_t)row * S;
    const float4* in4 = reinterpret_cast<const float4*>(x + base);

    float4 v[8];
    float s = 0.f, ss = 0.f;
    #pragma unroll
    for (int i = 0; i < 8; i++) {
        v[i] = in4[lane + 32 * i];
        s  += v[i].x + v[i].y + v[i].z + v[i].w;
        ss += v[i].x * v[i].x + v[i].y * v[i].y + v[i].z * v[i].z + v[i].w * v[i].w;
    }
    #pragma unroll
    for (int o = 16; o; o >>= 1) {
        s  += __shfl_xor_sync(0xFFFFFFFFu, s,  o);
        ss += __shfl_xor_sync(0xFFFFFFFFu, ss, o);
    }
    const float mean = s * (1.0f / S);

    float mx = 0.f;
    #pragma unroll
    for (int i = 0; i < 8; i++) {
        mx = fmaxf(mx, fabsf(v[i].x - mean));
        mx = fmaxf(mx, fabsf(v[i].y - mean));
        mx = fmaxf(mx, fabsf(v[i].z - mean));
        mx = fmaxf(mx, fabsf(v[i].w - mean));
    }
    #pragma unroll
    for (int o = 16; o; o >>= 1)
        mx = fmaxf(mx, __shfl_xor_sync(0xFFFFFFFFu, mx, o));
    mx = fmaxf(mx, 1e-20f);

    const float rss = fmaxf(ss - s * mean, 0.0f);
    const float inv_nrm = 1.0f / (sqrtf(rss) + 1e-8f);
    const float qmul = 127.0f / mx;

    if (lane == 0) g_scale[row] = mx * inv_nrm * (1.0f / 127.0f);

    uint32_t* out = reinterpret_cast<uint32_t*>(g_xq + base);
    #pragma unroll
    for (int i = 0; i < 8; i++) {
        int a0 = __float2int_rn((v[i].x - mean) * qmul);
        int a1 = __float2int_rn((v[i].y - mean) * qmul);
        int a2 = __float2int_rn((v[i].z - mean) * qmul);
        int a3 = __float2int_rn((v[i].w - mean) * qmul);
        uint32_t w = (a0 & 0xFF) | ((a1 & 0xFF) << 8) | ((a2 & 0xFF) << 16)
                   | (((uint32_t)a3 & 0xFF) << 24);
        out[lane + 32 * i] = w;
    }
}

// ---------------------------------------------------------------------------
// Kernel 2: int8 Gram tile (8 warps of 64x32), 3-stage cp.async, single sync
// per chunk, diagonal B-elision, strictly-lower warp-tile MMA elision,
// per-row-scale epilogue + masked |.| sum.
// ---------------------------------------------------------------------------
__global__ __launch_bounds__(TPB, 2) void gram_abs_kernel() {
    extern __shared__ __align__(128) char dsmem[];
    __shared__ float sScA[BM];
    __shared__ float sScB[BN];
    __shared__ float s_red[8];

    const int tid  = threadIdx.x;
    const int wid  = tid >> 5;
    const int lane = tid & 31;
    const int warp_m = wid & 1;            // 2 x 64 rows
    const int warp_n = wid >> 1;           // 4 x 32 cols

    const int bx = blockIdx.x;
    const int batch = bx / TILES_PER_BATCH;
    int t = bx % TILES_PER_BATCH;
    int ti = 0;
    while (t >= 8 - ti) { t -= 8 - ti; ti++; }
    const int tj = ti + t;
    const bool diag = (ti == tj);
    // In diagonal block-tiles, warp tiles with rows 64-127 x cols 0-63 are
    // entirely strictly-lower -> fully masked in the epilogue. Skip their work.
    const bool dead_warp = diag && (warp_m == 1) && (warp_n < 2);

    const int8_t* gA = g_xq + ((size_t)batch * C + ti * BM) * S;
    const int8_t* gB = g_xq + ((size_t)batch * C + tj * BN) * S;

    // stage row scales (256 threads: 128 A + 128 B)
    if (tid < BM) sScA[tid] = g_scale[batch * C + ti * BM + tid];
    else          sScB[tid - BM] = g_scale[batch * C + tj * BN + (tid - BM)];

    const uint32_t smem_base = (uint32_t)__cvta_generic_to_shared(dsmem);

    auto load_chunk = [&](int cch, int stage) {
        const int k0 = cch * BKB;
        const uint32_t sA = smem_base + stage * STAGE_BYTES;
        const uint32_t sB = sA + TILE_BYTES;
        #pragma unroll
        for (int it = 0; it < 4; it++) {
            int idx = it * TPB + tid;          // 0..1023
            int r   = idx >> 3;
            int c16 = idx & 7;                 // 16B chunk within 128B row
            uint32_t dst = swzB(r, c16 * 16);
            const size_t goff = (size_t)r * S + k0 + c16 * 16;
            cp_async16(sA + dst, gA + goff);
            if (!diag) cp_async16(sB + dst, gB + goff);
        }
    };

    // ldmatrix lane geometry (byte columns)
    const int a_row  = warp_m * 64 + (lane & 15);
    const int a_colB = (lane >> 4) * 16;
    const int b_row  = warp_n * 32 + (lane & 7) + ((lane >> 4) << 3);
    const int b_colB = ((lane >> 3) & 1) * 16;

    int acc[4][4][4];
    #pragma unroll
    for (int i = 0; i < 4; i++)
        #pragma unroll
        for (int j = 0; j < 4; j++)
            #pragma unroll
            for (int r = 0; r < 4; r++) acc[i][j][r] = 0;

    load_chunk(0, 0); CP_COMMIT();
    load_chunk(1, 1); CP_COMMIT();

    for (int cch = 0; cch < NCHUNK; cch++) {
        const int stage = cch % STAGES;
        CP_WAIT(1);
        __syncthreads();   // chunk cch resident; compute(cch-1) done by all warps

        if (cch + 2 < NCHUNK) {
            load_chunk(cch + 2, (cch + 2) % STAGES);
            CP_COMMIT();
        }

        if (!dead_warp) {
            const uint32_t sA = smem_base + stage * STAGE_BYTES;
            const uint32_t sB = diag ? sA : (sA + TILE_BYTES);

            #pragma unroll
            for (int kk = 0; kk < 4; kk++) {           // 4 x k32 per 128B chunk
                const int kb = kk * 32;
                uint32_t a[4][4];
                #pragma unroll
                for (int mf = 0; mf < 4; mf++) {
                    uint32_t addr = sA + swzB(a_row + mf * 16, kb + a_colB);
                    ldm_x4(a[mf][0], a[mf][1], a[mf][2], a[mf][3], addr);
                }
                uint32_t b[4][2];
                {
                    uint32_t addr0 = sB + swzB(b_row, kb + b_colB);
                    ldm_x4(b[0][0], b[0][1], b[1][0], b[1][1], addr0);
                    uint32_t addr1 = sB + swzB(b_row + 16, kb + b_colB);
                    ldm_x4(b[2][0], b[2][1], b[3][0], b[3][1], addr1);
                }
                #pragma unroll
                for (int mf = 0; mf < 4; mf++)
                    #pragma unroll
                    for (int nf = 0; nf < 4; nf++)
                        mma16832_s8(acc[mf][nf], a[mf], b[nf]);
            }
        }
        // no trailing sync: top-of-loop sync of iter cch+1 protects stage reuse
    }

    // Epilogue: rescale each entry by sA[i]*sB[j], mask strictly-upper, abs-sum
    const int groupID = lane >> 2;
    const int tid4    = lane & 3;
    float lsum = 0.0f;
    if (!dead_warp) {
        #pragma unroll
        for (int mf = 0; mf < 4; mf++) {
            const int li0 = warp_m * 64 + mf * 16 + groupID;
            const int li1 = li0 + 8;
            const float sa0 = sScA[li0];
            const float sa1 = sScA[li1];
            const int gi0 = ti * BM + li0;
            const int gi1 = ti * BM + li1;
            #pragma unroll
            for (int nf = 0; nf < 4; nf++) {
                const int lj = warp_n * 32 + nf * 8 + tid4 * 2;
                const int gj = tj * BN + lj;
                const float sb0 = sScB[lj];
                const float sb1 = sScB[lj + 1];
                if (gj     > gi0) lsum += fabsf((float)acc[mf][nf][0] * sa0 * sb0);
                if (gj + 1 > gi0) lsum += fabsf((float)acc[mf][nf][1] * sa0 * sb1);
                if (gj     > gi1) lsum += fabsf((float)acc[mf][nf][2] * sa1 * sb0);
                if (gj + 1 > gi1) lsum += fabsf((float)acc[mf][nf][3] * sa1 * sb1);
            }
        }
        #pragma unroll
        for (int o = 16; o; o >>= 1) lsum += __shfl_xor_sync(0xFFFFFFFFu, lsum, o);
    }

    if (lane == 0) s_red[wid] = lsum;
    __syncthreads();
    if (tid == 0) {
        float bsum = 0.f;
        #pragma unroll
        for (int w = 0; w < 8; w++) bsum += s_red[w];
        g_partials[bx] = bsum;
    }
}

// ---------------------------------------------------------------------------
// Kernel 3: deterministic final reduction + scaling.
// avg = U / (comb * N), comb = C*(C-1)/2 (total offdiag = 2U)
// ---------------------------------------------------------------------------
__global__ __launch_bounds__(256) void finalize_kernel(float* __restrict__ out) {
    float s = 0.0f;
    for (int i = threadIdx.x; i < NBLK2; i += 256) s += g_partials[i];
    #pragma unroll
    for (int o = 16; o; o >>= 1) s += __shfl_xor_sync(0xFFFFFFFFu, s, o);

    __shared__ float red[8];
    const int wid = threadIdx.x >> 5;
    if ((threadIdx.x & 31) == 0) red[wid] = s;
    __syncthreads();
    if (threadIdx.x == 0) {
        float tot = 0.f;
        #pragma unroll
        for (int w = 0; w < 8; w++) tot += red[w];
        const float comb = (float)C * (C - 1) * 0.5f;
        out[0] = tot / (comb * (float)NB);
    }
}

// ---------------------------------------------------------------------------
extern "C" void kernel_launch(void* const* d_in, const int* in_sizes, int n_in,
                              void* d_out, int out_size) {
    const float* x = (const float*)d_in[0];
    float* out = (float*)d_out;

    cudaFuncSetAttribute(gram_abs_kernel,
                         cudaFuncAttributeMaxDynamicSharedMemorySize, DSMEM_BYTES);

    normalize_kernel<<<NB * C / 8, 256>>>(x);
    gram_abs_kernel<<<NBLK2, TPB, DSMEM_BYTES>>>();
    finalize_kernel<<<1, 256>>>(out);
}